// round 2
// baseline (speedup 1.0000x reference)
#include <cuda_runtime.h>
#include <math.h>

#define NB 256
#define TT 64
#define DD 1024
#define HH 1024
#define GG 4096
#define LL 16

// ---------------- scratch (device globals; no allocations allowed) -------------
__device__ float g_XW[NB * TT * GG];     // x @ Wx + b, per (n,t): 268 MB
__device__ float g_P[NB * LL * GG];      // P[n,l,:] = A_flat[n,:,l] @ Wattn: 64 MB
__device__ float g_AT[NB * LL * HH];     // A transposed to (n,l,h): 16 MB
__device__ float g_hA[NB * HH];          // h ping
__device__ float g_hB[NB * HH];          // h pong
__device__ float g_c[NB * HH];           // cell state
__device__ float g_attnZ[NB * GG];       // per-step: XW[:,t,:] + sum_l w_l P[n,l,:]

// ---------------- init: transpose A, compute h0 = mean, c0 = h0 ---------------
__global__ void init_kernel(const float* __restrict__ A) {
    int idx = blockIdx.x * blockDim.x + threadIdx.x;   // n*H + h
    int n = idx >> 10, h = idx & 1023;
    const float4* a4 = reinterpret_cast<const float4*>(A + (size_t)(n * HH + h) * 16);
    float s = 0.f;
#pragma unroll
    for (int q = 0; q < 4; q++) {
        float4 v = a4[q];
        g_AT[(size_t)(n * LL + q * 4 + 0) * HH + h] = v.x;
        g_AT[(size_t)(n * LL + q * 4 + 1) * HH + h] = v.y;
        g_AT[(size_t)(n * LL + q * 4 + 2) * HH + h] = v.z;
        g_AT[(size_t)(n * LL + q * 4 + 3) * HH + h] = v.w;
        s += v.x + v.y + v.z + v.w;
    }
    float h0 = s * (1.0f / 16.0f);
    g_hA[idx] = h0;
    g_c[idx] = h0;
}

// ---------------- generic 128x128x16 double-buffered SGEMM --------------------
// C[m, j] = sum_k Amat[m, k] * Bmat[k, j] (+ bias[j])
// grid.x = M/128, grid.y = Ncols/128, 256 threads, 8x8 microtile.
template <bool BIAS>
__global__ __launch_bounds__(256)
void sgemm128(const float* __restrict__ Ag0, const float* __restrict__ Bg0,
              const float* __restrict__ bias, float* __restrict__ C,
              int K, int Ncols) {
    __shared__ __align__(16) float As[2][16][132];   // padded (bank spread), rows 16B-aligned
    __shared__ __align__(16) float Bs[2][16][128];

    const int tid = threadIdx.x;
    const int m0 = blockIdx.x * 128, n0 = blockIdx.y * 128;
    const int trow = tid >> 4, tcol = tid & 15;
    const int ar = tid >> 2, ak = (tid & 3) * 4;     // A-tile: 128x16 = 512 f4, 2/thread
    const int bk = tid >> 5, bc = (tid & 31) * 4;    // B-tile: 16x128 = 512 f4, 2/thread
    const float* Ag = Ag0 + (size_t)m0 * K;
    const float* Bg = Bg0 + n0;

    float acc[8][8];
#pragma unroll
    for (int i = 0; i < 8; i++)
#pragma unroll
        for (int j = 0; j < 8; j++) acc[i][j] = 0.f;

    float4 pa0, pa1, pb0, pb1;
    pa0 = *(const float4*)(Ag + (size_t)ar * K + ak);
    pa1 = *(const float4*)(Ag + (size_t)(ar + 64) * K + ak);
    pb0 = *(const float4*)(Bg + (size_t)bk * Ncols + bc);
    pb1 = *(const float4*)(Bg + (size_t)(bk + 8) * Ncols + bc);

    As[0][ak + 0][ar] = pa0.x; As[0][ak + 1][ar] = pa0.y;
    As[0][ak + 2][ar] = pa0.z; As[0][ak + 3][ar] = pa0.w;
    As[0][ak + 0][ar + 64] = pa1.x; As[0][ak + 1][ar + 64] = pa1.y;
    As[0][ak + 2][ar + 64] = pa1.z; As[0][ak + 3][ar + 64] = pa1.w;
    *(float4*)&Bs[0][bk][bc] = pb0;
    *(float4*)&Bs[0][bk + 8][bc] = pb1;
    __syncthreads();

    int buf = 0;
    const int KT = K >> 4;
    for (int kt = 0; kt < KT; kt++) {
        if (kt + 1 < KT) {
            const float* Agk = Ag + ((kt + 1) << 4);
            const float* Bgk = Bg + (size_t)((kt + 1) << 4) * Ncols;
            pa0 = *(const float4*)(Agk + (size_t)ar * K + ak);
            pa1 = *(const float4*)(Agk + (size_t)(ar + 64) * K + ak);
            pb0 = *(const float4*)(Bgk + (size_t)bk * Ncols + bc);
            pb1 = *(const float4*)(Bgk + (size_t)(bk + 8) * Ncols + bc);
        }
#pragma unroll
        for (int k = 0; k < 16; k++) {
            float ra[8], rb[8];
            *(float4*)(ra)     = *(const float4*)&As[buf][k][trow * 8];
            *(float4*)(ra + 4) = *(const float4*)&As[buf][k][trow * 8 + 4];
            *(float4*)(rb)     = *(const float4*)&Bs[buf][k][tcol * 8];
            *(float4*)(rb + 4) = *(const float4*)&Bs[buf][k][tcol * 8 + 4];
#pragma unroll
            for (int i = 0; i < 8; i++)
#pragma unroll
                for (int j = 0; j < 8; j++) acc[i][j] += ra[i] * rb[j];
        }
        if (kt + 1 < KT) {
            int nb = buf ^ 1;
            As[nb][ak + 0][ar] = pa0.x; As[nb][ak + 1][ar] = pa0.y;
            As[nb][ak + 2][ar] = pa0.z; As[nb][ak + 3][ar] = pa0.w;
            As[nb][ak + 0][ar + 64] = pa1.x; As[nb][ak + 1][ar + 64] = pa1.y;
            As[nb][ak + 2][ar + 64] = pa1.z; As[nb][ak + 3][ar + 64] = pa1.w;
            *(float4*)&Bs[nb][bk][bc] = pb0;
            *(float4*)&Bs[nb][bk + 8][bc] = pb1;
            __syncthreads();
            buf = nb;
        }
    }

#pragma unroll
    for (int i = 0; i < 8; i++) {
        size_t row = (size_t)(m0 + trow * 8 + i);
#pragma unroll
        for (int jq = 0; jq < 2; jq++) {
            float4 v;
            v.x = acc[i][jq * 4 + 0]; v.y = acc[i][jq * 4 + 1];
            v.z = acc[i][jq * 4 + 2]; v.w = acc[i][jq * 4 + 3];
            int cb = n0 + tcol * 8 + jq * 4;
            if (BIAS) {
                v.x += bias[cb]; v.y += bias[cb + 1];
                v.z += bias[cb + 2]; v.w += bias[cb + 3];
            }
            *(float4*)(C + row * Ncols + cb) = v;
        }
    }
}

// ---------------- per-step: scores -> softmax -> attnZ = XW + sum_l w_l P -----
__global__ __launch_bounds__(512)
void attn_kernel(int t) {
    const int n = blockIdx.x;
    const int tid = threadIdx.x;
    const int warp = tid >> 5, lane = tid & 31;
    __shared__ float sw[16];

    const float* hcur = (t & 1) ? g_hB : g_hA;
    const float* hp = hcur + (size_t)n * HH;
    const float* ap = g_AT + ((size_t)n * LL + warp) * HH;

    float acc = 0.f;
    for (int k = lane; k < HH; k += 32) acc += hp[k] * ap[k];
#pragma unroll
    for (int o = 16; o > 0; o >>= 1) acc += __shfl_xor_sync(0xffffffffu, acc, o);
    if (lane == 0) sw[warp] = acc * 0.03125f;   // 1/sqrt(1024)
    __syncthreads();

    if (warp == 0) {
        float s = (lane < 16) ? sw[lane] : -1e30f;
        float m = s;
#pragma unroll
        for (int o = 16; o > 0; o >>= 1) m = fmaxf(m, __shfl_xor_sync(0xffffffffu, m, o));
        float e = (lane < 16) ? expf(s - m) : 0.f;
        float tot = e;
#pragma unroll
        for (int o = 16; o > 0; o >>= 1) tot += __shfl_xor_sync(0xffffffffu, tot, o);
        if (lane < 16) sw[lane] = e / tot;
    }
    __syncthreads();

    float wl[16];
#pragma unroll
    for (int l = 0; l < 16; l++) wl[l] = sw[l];

    const float4* xw4 = (const float4*)(g_XW + ((size_t)n * TT + t) * GG);
    const float4* p4  = (const float4*)(g_P + (size_t)n * LL * GG);
    float4* oz4 = (float4*)(g_attnZ + (size_t)n * GG);
#pragma unroll
    for (int it = 0; it < 2; it++) {
        int c = tid + it * 512;            // GG/4 = 1024 float4s
        float4 a = xw4[c];
#pragma unroll
        for (int l = 0; l < 16; l++) {
            float4 pv = p4[(size_t)l * (GG / 4) + c];
            float w = wl[l];
            a.x += w * pv.x; a.y += w * pv.y; a.z += w * pv.z; a.w += w * pv.w;
        }
        oz4[c] = a;
    }
}

// ---------------- per-step: h@Wh GEMM + fused gates + state update ------------
// Block tile: 64 rows (n) x 4 gate-strips of 32 cols. Thread (ty,tx): 8 rows,
// one column jh = jj+tx in each of the 4 gate slices -> gates computed locally.
__global__ __launch_bounds__(256)
void step_kernel(const float* __restrict__ Wh, float* __restrict__ out, int t) {
    __shared__ __align__(16) float Hs[2][16][68];
    __shared__ __align__(16) float Ws[2][16][128];

    const int tid = threadIdx.x;
    const int ty = tid >> 5, tx = tid & 31;
    const int bn = blockIdx.x * 64;
    const int jj = blockIdx.y * 32;

    const float* hcur = (t & 1) ? g_hB : g_hA;
    float* hnxt = (t & 1) ? g_hA : g_hB;

    const int hr = tid >> 2, hk = (tid & 3) * 4;     // H-tile 64x16 = 256 f4, 1/thread
    const int wk = tid >> 5, wc = tid & 31;          // W-tile 16x128 = 512 f4, 2/thread
    const int ws = wc >> 3, wq = (wc & 7) * 4;
    const size_t wcol = (size_t)(ws * 1024 + jj + wq);
    const float* Hg = hcur + (size_t)bn * HH;

    float acc[8][4];
#pragma unroll
    for (int i = 0; i < 8; i++)
#pragma unroll
        for (int s = 0; s < 4; s++) acc[i][s] = 0.f;

    float4 ph, pw0, pw1;
    ph  = *(const float4*)(Hg + (size_t)hr * HH + hk);
    pw0 = *(const float4*)(Wh + (size_t)wk * GG + wcol);
    pw1 = *(const float4*)(Wh + (size_t)(wk + 8) * GG + wcol);
    Hs[0][hk + 0][hr] = ph.x; Hs[0][hk + 1][hr] = ph.y;
    Hs[0][hk + 2][hr] = ph.z; Hs[0][hk + 3][hr] = ph.w;
    *(float4*)&Ws[0][wk][wc * 4] = pw0;
    *(float4*)&Ws[0][wk + 8][wc * 4] = pw1;
    __syncthreads();

    int buf = 0;
    for (int kt = 0; kt < 64; kt++) {
        if (kt < 63) {
            int k0 = (kt + 1) * 16;
            ph  = *(const float4*)(Hg + (size_t)hr * HH + k0 + hk);
            pw0 = *(const float4*)(Wh + (size_t)(k0 + wk) * GG + wcol);
            pw1 = *(const float4*)(Wh + (size_t)(k0 + wk + 8) * GG + wcol);
        }
#pragma unroll
        for (int k = 0; k < 16; k++) {
            float ra[8];
            *(float4*)(ra)     = *(const float4*)&Hs[buf][k][ty * 8];
            *(float4*)(ra + 4) = *(const float4*)&Hs[buf][k][ty * 8 + 4];
            float rb0 = Ws[buf][k][tx];
            float rb1 = Ws[buf][k][32 + tx];
            float rb2 = Ws[buf][k][64 + tx];
            float rb3 = Ws[buf][k][96 + tx];
#pragma unroll
            for (int i = 0; i < 8; i++) {
                acc[i][0] += ra[i] * rb0;
                acc[i][1] += ra[i] * rb1;
                acc[i][2] += ra[i] * rb2;
                acc[i][3] += ra[i] * rb3;
            }
        }
        if (kt < 63) {
            int nb = buf ^ 1;
            Hs[nb][hk + 0][hr] = ph.x; Hs[nb][hk + 1][hr] = ph.y;
            Hs[nb][hk + 2][hr] = ph.z; Hs[nb][hk + 3][hr] = ph.w;
            *(float4*)&Ws[nb][wk][wc * 4] = pw0;
            *(float4*)&Ws[nb][wk + 8][wc * 4] = pw1;
            __syncthreads();
            buf = nb;
        }
    }

#pragma unroll
    for (int i = 0; i < 8; i++) {
        int n = bn + ty * 8 + i;
        int jh = jj + tx;
        size_t zb = (size_t)n * GG + jh;
        float a0 = acc[i][0] + g_attnZ[zb];
        float a1 = acc[i][1] + g_attnZ[zb + 1024];
        float a2 = acc[i][2] + g_attnZ[zb + 2048];
        float a3 = acc[i][3] + g_attnZ[zb + 3072];
        float gi = 1.f / (1.f + expf(-a0));
        float gf = 1.f / (1.f + expf(-a1));
        float go = 1.f / (1.f + expf(-a2));
        float gg = tanhf(a3);
        size_t hidx = (size_t)n * HH + jh;
        float cn = gf * g_c[hidx] + gi * gg;
        g_c[hidx] = cn;
        float hn = go * tanhf(cn);
        hnxt[hidx] = hn;
        out[((size_t)n * TT + t) * HH + jh] = hn;
    }
}

// ---------------- launch ------------------------------------------------------
extern "C" void kernel_launch(void* const* d_in, const int* in_sizes, int n_in,
                              void* d_out, int out_size) {
    const float* x     = (const float*)d_in[0];
    const float* A     = (const float*)d_in[1];
    const float* Wx    = (const float*)d_in[2];
    const float* Wh    = (const float*)d_in[3];
    const float* Wattn = (const float*)d_in[4];
    const float* b     = (const float*)d_in[5];
    float* out = (float*)d_out;

    float *p_xw, *p_p, *p_at;
    cudaGetSymbolAddress((void**)&p_xw, g_XW);
    cudaGetSymbolAddress((void**)&p_p, g_P);
    cudaGetSymbolAddress((void**)&p_at, g_AT);

    // Phase 0: transpose A, init h0/c0
    init_kernel<<<(NB * HH) / 256, 256>>>(A);

    // Phase 1a: XW[n*T+t, :] = x @ Wx + b   (M=16384, K=1024, N=4096)
    {
        dim3 g((NB * TT) / 128, GG / 128);
        sgemm128<true><<<g, 256>>>(x, Wx, b, p_xw, DD, GG);
    }
    // Phase 1b: P[n*16+l, :] = AT @ Wattn   (M=4096, K=1024, N=4096)
    {
        dim3 g((NB * LL) / 128, GG / 128);
        sgemm128<false><<<g, 256>>>(p_at, Wattn, nullptr, p_p, HH, GG);
    }

    // Phase 2: sequential scan over T
    for (int t = 0; t < TT; t++) {
        attn_kernel<<<NB, 512>>>(t);
        dim3 gs(NB / 64, HH / 32);
        step_kernel<<<gs, 256>>>(Wh, out, t);
    }
}

// round 4
// speedup vs baseline: 2.0480x; 2.0480x over previous
#include <cuda_runtime.h>
#include <cuda_bf16.h>
#include <math.h>
#include <stdint.h>

#define NB 256
#define TT 64
#define HH 1024
#define GG 4096
#define LL 16
#define KP 3072   // 3-term split folded into K

__device__ __forceinline__ uint32_t smem_u32(const void* p) {
    uint32_t a;
    asm("{ .reg .u64 t; cvta.to.shared.u64 t, %1; cvt.u32.u64 %0, t; }" : "=r"(a) : "l"(p));
    return a;
}
#define CP16(dst, src) asm volatile("cp.async.cg.shared.global [%0], [%1], 16;" :: "r"(dst), "l"(src) : "memory")
#define CP_COMMIT() asm volatile("cp.async.commit_group;" ::: "memory")
#define CP_WAIT1() asm volatile("cp.async.wait_group 1;" ::: "memory")
#define LDSM4(r0, r1, r2, r3, addr) \
    asm volatile("ldmatrix.sync.aligned.m8n8.x4.shared.b16 {%0,%1,%2,%3}, [%4];" \
        : "=r"(r0), "=r"(r1), "=r"(r2), "=r"(r3) : "r"(addr))
#define MMA16816(d, a, b) \
    asm volatile("mma.sync.aligned.m16n8k16.row.col.f32.bf16.bf16.f32 " \
        "{%0,%1,%2,%3}, {%4,%5,%6,%7}, {%8,%9}, {%0,%1,%2,%3};" \
        : "+f"((d)[0]), "+f"((d)[1]), "+f"((d)[2]), "+f"((d)[3]) \
        : "r"((a)[0]), "r"((a)[1]), "r"((a)[2]), "r"((a)[3]), "r"((b)[0]), "r"((b)[1]))

// ------------------------------------------------ scratch
__device__ float g_XW[(size_t)NB * TT * GG];      // permuted cols, fp32
__device__ float g_P[(size_t)NB * LL * GG];       // permuted cols, fp32
__device__ float g_AT[(size_t)NB * LL * HH];      // fp32 for scores
__device__ float g_attnZ[(size_t)NB * GG];        // permuted cols
__device__ float g_w[NB * LL];
__device__ float g_h[NB * HH];
__device__ float g_c[NB * HH];
__device__ float g_bperm[GG];
__device__ __nv_bfloat16 g_xs[(size_t)NB * TT * KP];     // [xhi|xlo|xhi]
__device__ __nv_bfloat16 g_ATs[(size_t)NB * LL * KP];    // [hi|lo|hi]
__device__ __nv_bfloat16 g_Wxs[(size_t)GG * KP];         // [hi|hi|lo] (B side)
__device__ __nv_bfloat16 g_Whs[(size_t)GG * KP];
__device__ __nv_bfloat16 g_Was[(size_t)GG * KP];
__device__ __nv_bfloat16 g_hsA[(size_t)NB * KP];         // h ping [hi|lo|hi]
__device__ __nv_bfloat16 g_hsB[(size_t)NB * KP];         // h pong

// ------------------------------------------------ prep kernels
__global__ void x_split_kernel(const float* __restrict__ x) {
    size_t gid = (size_t)blockIdx.x * 256 + threadIdx.x;  // float4 id
    size_t r = gid >> 8;
    int kq = (int)(gid & 255);
    float4 v = ((const float4*)x)[gid];
    __nv_bfloat162 h0 = __floats2bfloat162_rn(v.x, v.y);
    __nv_bfloat162 h1 = __floats2bfloat162_rn(v.z, v.w);
    float2 f0 = __bfloat1622float2(h0), f1 = __bfloat1622float2(h1);
    __nv_bfloat162 l0 = __floats2bfloat162_rn(v.x - f0.x, v.y - f0.y);
    __nv_bfloat162 l1 = __floats2bfloat162_rn(v.z - f1.x, v.w - f1.y);
    __nv_bfloat162* base = (__nv_bfloat162*)(g_xs + r * KP);
    base[kq * 2] = h0;         base[kq * 2 + 1] = h1;
    base[512 + kq * 2] = l0;   base[512 + kq * 2 + 1] = l1;
    base[1024 + kq * 2] = h0;  base[1024 + kq * 2 + 1] = h1;
}

__global__ void at_prep_kernel(const float* __restrict__ A) {
    int idx = blockIdx.x * 256 + threadIdx.x;  // n*1024 + h
    int n = idx >> 10, h = idx & 1023;
    const float4* a4 = (const float4*)(A + (size_t)idx * 16);
    float s = 0.f;
#pragma unroll
    for (int q = 0; q < 4; q++) {
        float4 v = a4[q];
        float vv[4] = {v.x, v.y, v.z, v.w};
#pragma unroll
        for (int e = 0; e < 4; e++) {
            int l = q * 4 + e;
            float val = vv[e];
            g_AT[((size_t)n * LL + l) * HH + h] = val;
            __nv_bfloat16 hi = __float2bfloat16(val);
            __nv_bfloat16 lo = __float2bfloat16(val - __bfloat162float(hi));
            size_t o = ((size_t)n * LL + l) * KP + h;
            g_ATs[o] = hi; g_ATs[o + 1024] = lo; g_ATs[o + 2048] = hi;
            s += val;
        }
    }
    float h0 = s * (1.0f / 16.0f);
    g_h[idx] = h0;
    g_c[idx] = h0;
    __nv_bfloat16 hh = __float2bfloat16(h0);
    __nv_bfloat16 hl = __float2bfloat16(h0 - __bfloat162float(hh));
    size_t o = (size_t)n * KP + h;
    g_hsA[o] = hh; g_hsA[o + 1024] = hl; g_hsA[o + 2048] = hh;
}

// transpose + split + permute: col c = g*1024+u -> rp = ((u>>3)<<5)|(g<<3)|(u&7)
__global__ void wsplit_kernel(const float* __restrict__ W, __nv_bfloat16* __restrict__ Ws) {
    __shared__ float tile[32][33];
    int c0 = blockIdx.x * 32, k0 = blockIdx.y * 32;
    int tx = threadIdx.x;
    for (int i = threadIdx.y; i < 32; i += 8)
        tile[i][tx] = W[(size_t)(k0 + i) * GG + c0 + tx];
    __syncthreads();
    for (int i = threadIdx.y; i < 32; i += 8) {
        int c = c0 + i;
        int u = c & 1023, g = c >> 10;
        int rp = ((u >> 3) << 5) | (g << 3) | (u & 7);
        float v = tile[tx][i];
        __nv_bfloat16 hi = __float2bfloat16(v);
        __nv_bfloat16 lo = __float2bfloat16(v - __bfloat162float(hi));
        size_t o = (size_t)rp * KP + k0 + tx;
        Ws[o] = hi; Ws[o + 1024] = hi; Ws[o + 2048] = lo;
    }
}

__global__ void bias_perm_kernel(const float* __restrict__ b) {
    int idx = blockIdx.x * 256 + threadIdx.x;   // permuted col
    int g = (idx >> 3) & 3;
    int u = (idx & 7) | ((idx >> 5) << 3);
    g_bperm[idx] = b[g * 1024 + u];
}

// ------------------------------------------------ mma.sync bf16 GEMM, K'=3072
// C[m0:+BM, n0:+BN] = A'[*, 3072] @ B'[*, 3072]^T
// EPI: 0 plain fp32 store, 1 +bias, 2 fused LSTM gates (needs WN==32)
template <int BM, int BN, int WARPS_M, int WARPS_N, int EPI>
__global__ void __launch_bounds__(WARPS_M * WARPS_N * 32)
gemm_mma(const __nv_bfloat16* __restrict__ Ag, const __nv_bfloat16* __restrict__ Bg,
         float* __restrict__ Cout, const float* __restrict__ addv,
         __nv_bfloat16* __restrict__ hnext, float* __restrict__ out, int t)
{
    constexpr int NTH = WARPS_M * WARPS_N * 32;
    constexpr int WM = BM / WARPS_M, WN = BN / WARPS_N;
    constexpr int MT = WM / 16, NT2 = WN / 8;
    constexpr int KC = KP / 64;
    constexpr int ABUF = BM * 128, BBUF = BN * 128;

    extern __shared__ char smem[];
    const uint32_t sA = smem_u32(smem);
    const uint32_t sB = sA + 2 * ABUF;
    const int tid = threadIdx.x, lane = tid & 31, warp = tid >> 5;
    const int wm0 = (warp / WARPS_N) * WM, wn0 = (warp % WARPS_N) * WN;
    const int m0 = blockIdx.y * BM, n0 = blockIdx.x * BN;
    const __nv_bfloat16* Abase = Ag + (size_t)m0 * KP;
    const __nv_bfloat16* Bbase = Bg + (size_t)n0 * KP;

    float acc[MT][NT2][4];
#pragma unroll
    for (int i = 0; i < MT; i++)
#pragma unroll
        for (int j = 0; j < NT2; j++)
#pragma unroll
            for (int e = 0; e < 4; e++) acc[i][j][e] = 0.f;

#define ISSUE(kc, buf) do { \
    const __nv_bfloat16* As_ = Abase + (kc) * 64; \
    _Pragma("unroll") \
    for (int i = 0; i < BM * 8 / NTH; i++) { \
        int idx = tid + i * NTH, r = idx >> 3, q = idx & 7; \
        CP16(sA + (buf) * ABUF + r * 128 + (((q ^ (r & 7)) << 4)), As_ + (size_t)r * KP + q * 8); \
    } \
    const __nv_bfloat16* Bs_ = Bbase + (kc) * 64; \
    _Pragma("unroll") \
    for (int i = 0; i < BN * 8 / NTH; i++) { \
        int idx = tid + i * NTH, r = idx >> 3, q = idx & 7; \
        CP16(sB + (buf) * BBUF + r * 128 + (((q ^ (r & 7)) << 4)), Bs_ + (size_t)r * KP + q * 8); \
    } \
} while (0)

    ISSUE(0, 0); CP_COMMIT();
    ISSUE(1, 1); CP_COMMIT();

    for (int kc = 0; kc < KC; kc++) {
        CP_WAIT1();
        __syncthreads();
        const int buf = kc & 1;
        const uint32_t a0b = sA + buf * ABUF, b0b = sB + buf * BBUF;
#pragma unroll
        for (int ks = 0; ks < 4; ks++) {
            uint32_t af[MT][4], bf[NT2][2];
#pragma unroll
            for (int mt = 0; mt < MT; mt++) {
                int r = wm0 + mt * 16 + (lane & 15);
                int q = ks * 2 + (lane >> 4);
                LDSM4(af[mt][0], af[mt][1], af[mt][2], af[mt][3],
                      a0b + r * 128 + (((q ^ (r & 7)) << 4)));
            }
#pragma unroll
            for (int p = 0; p < NT2 / 2; p++) {
                int n = wn0 + p * 16 + (lane & 7) + ((lane >> 4) << 3);
                int q = ks * 2 + ((lane >> 3) & 1);
                LDSM4(bf[2 * p][0], bf[2 * p][1], bf[2 * p + 1][0], bf[2 * p + 1][1],
                      b0b + n * 128 + (((q ^ (n & 7)) << 4)));
            }
#pragma unroll
            for (int mt = 0; mt < MT; mt++)
#pragma unroll
                for (int nt = 0; nt < NT2; nt++)
                    MMA16816(acc[mt][nt], af[mt], bf[nt]);
        }
        __syncthreads();
        if (kc + 2 < KC) ISSUE(kc + 2, buf);
        CP_COMMIT();
    }
#undef ISSUE

    const int l4 = lane >> 2, q2 = (lane & 3) * 2;
    if (EPI != 2) {
#pragma unroll
        for (int mt = 0; mt < MT; mt++) {
            int r0 = m0 + wm0 + mt * 16 + l4;
#pragma unroll
            for (int nt = 0; nt < NT2; nt++) {
                int col = n0 + wn0 + nt * 8 + q2;
                float bx = 0.f, by = 0.f;
                if (EPI == 1) { bx = addv[col]; by = addv[col + 1]; }
                *(float2*)(Cout + (size_t)r0 * GG + col) =
                    make_float2(acc[mt][nt][0] + bx, acc[mt][nt][1] + by);
                *(float2*)(Cout + (size_t)(r0 + 8) * GG + col) =
                    make_float2(acc[mt][nt][2] + bx, acc[mt][nt][3] + by);
            }
        }
    } else {
        const int U0 = (((n0 + wn0) >> 5) << 3) + q2;
        const int cb = n0 + wn0 + q2;
#pragma unroll
        for (int mt = 0; mt < MT; mt++) {
#pragma unroll
            for (int rs = 0; rs < 2; rs++) {
                int row = m0 + wm0 + mt * 16 + l4 + rs * 8;
                const float* zr = addv + (size_t)row * GG + cb;
#pragma unroll
                for (int us = 0; us < 2; us++) {
                    float ai = acc[mt][0][rs * 2 + us] + zr[us];
                    float afv = acc[mt][1][rs * 2 + us] + zr[8 + us];
                    float ao = acc[mt][2][rs * 2 + us] + zr[16 + us];
                    float ag = acc[mt][3][rs * 2 + us] + zr[24 + us];
                    int u = U0 + us;
                    float gi = 1.f / (1.f + expf(-ai));
                    float gf = 1.f / (1.f + expf(-afv));
                    float go = 1.f / (1.f + expf(-ao));
                    float gg = tanhf(ag);
                    size_t hx = (size_t)row * HH + u;
                    float cn = gf * g_c[hx] + gi * gg;
                    g_c[hx] = cn;
                    float hn = go * tanhf(cn);
                    g_h[hx] = hn;
                    __nv_bfloat16 hh = __float2bfloat16(hn);
                    __nv_bfloat16 hl = __float2bfloat16(hn - __bfloat162float(hh));
                    size_t hb = (size_t)row * KP + u;
                    hnext[hb] = hh; hnext[hb + 1024] = hl; hnext[hb + 2048] = hh;
                    out[((size_t)row * TT + t) * HH + u] = hn;
                }
            }
        }
    }
}

// ------------------------------------------------ per-step small kernels
__global__ __launch_bounds__(512) void scores_kernel() {
    const int n = blockIdx.x;
    const int tid = threadIdx.x, warp = tid >> 5, lane = tid & 31;
    __shared__ float sw[16];
    const float* hp = g_h + (size_t)n * HH;
    const float* ap = g_AT + ((size_t)n * LL + warp) * HH;
    float acc = 0.f;
    for (int k = lane; k < HH; k += 32) acc += hp[k] * ap[k];
#pragma unroll
    for (int o = 16; o > 0; o >>= 1) acc += __shfl_xor_sync(0xffffffffu, acc, o);
    if (lane == 0) sw[warp] = acc * 0.03125f;
    __syncthreads();
    if (warp == 0) {
        float s = (lane < 16) ? sw[lane] : -1e30f;
        float m = s;
#pragma unroll
        for (int o = 16; o > 0; o >>= 1) m = fmaxf(m, __shfl_xor_sync(0xffffffffu, m, o));
        float e = (lane < 16) ? expf(s - m) : 0.f;
        float tot = e;
#pragma unroll
        for (int o = 16; o > 0; o >>= 1) tot += __shfl_xor_sync(0xffffffffu, tot, o);
        if (lane < 16) g_w[n * LL + lane] = e / tot;
    }
}

__global__ __launch_bounds__(256) void combine_kernel(int t) {
    const int n = blockIdx.x >> 2;
    const int c = ((blockIdx.x & 3) << 8) + threadIdx.x;  // float4 idx 0..1023
    float wl[16];
#pragma unroll
    for (int l = 0; l < 16; l++) wl[l] = g_w[n * LL + l];
    float4 a = ((const float4*)(g_XW + ((size_t)n * TT + t) * GG))[c];
    const float4* p4 = (const float4*)(g_P + (size_t)n * LL * GG);
#pragma unroll
    for (int l = 0; l < 16; l++) {
        float4 pv = p4[(size_t)l * (GG / 4) + c];
        float w = wl[l];
        a.x += w * pv.x; a.y += w * pv.y; a.z += w * pv.z; a.w += w * pv.w;
    }
    ((float4*)(g_attnZ + (size_t)n * GG))[c] = a;
}

// ------------------------------------------------ launch
extern "C" void kernel_launch(void* const* d_in, const int* in_sizes, int n_in,
                              void* d_out, int out_size) {
    const float* x = (const float*)d_in[0];
    const float* A = (const float*)d_in[1];
    const float* Wx = (const float*)d_in[2];
    const float* Wh = (const float*)d_in[3];
    const float* Wattn = (const float*)d_in[4];
    const float* b = (const float*)d_in[5];
    float* out = (float*)d_out;

    float *p_xw, *p_p, *p_bp, *p_z;
    __nv_bfloat16 *p_xs, *p_ats, *p_wxs, *p_whs, *p_was, *p_hsA, *p_hsB;
    cudaGetSymbolAddress((void**)&p_xw, g_XW);
    cudaGetSymbolAddress((void**)&p_p, g_P);
    cudaGetSymbolAddress((void**)&p_bp, g_bperm);
    cudaGetSymbolAddress((void**)&p_z, g_attnZ);
    cudaGetSymbolAddress((void**)&p_xs, g_xs);
    cudaGetSymbolAddress((void**)&p_ats, g_ATs);
    cudaGetSymbolAddress((void**)&p_wxs, g_Wxs);
    cudaGetSymbolAddress((void**)&p_whs, g_Whs);
    cudaGetSymbolAddress((void**)&p_was, g_Was);
    cudaGetSymbolAddress((void**)&p_hsA, g_hsA);
    cudaGetSymbolAddress((void**)&p_hsB, g_hsB);

    constexpr int SM_P1 = 2 * (128 + 128) * 128;  // 65536
    constexpr int SM_ST = 2 * (64 + 64) * 128;    // 32768
    cudaFuncSetAttribute((const void*)gemm_mma<128, 128, 2, 4, 1>,
                         cudaFuncAttributeMaxDynamicSharedMemorySize, SM_P1);
    cudaFuncSetAttribute((const void*)gemm_mma<128, 128, 2, 4, 0>,
                         cudaFuncAttributeMaxDynamicSharedMemorySize, SM_P1);
    cudaFuncSetAttribute((const void*)gemm_mma<64, 64, 2, 2, 2>,
                         cudaFuncAttributeMaxDynamicSharedMemorySize, SM_ST);

    // prep
    x_split_kernel<<<(NB * TT * HH / 4) / 256, 256>>>(x);
    at_prep_kernel<<<(NB * HH) / 256, 256>>>(A);
    {
        dim3 g(GG / 32, HH / 32), blk(32, 8);
        wsplit_kernel<<<g, blk>>>(Wx, p_wxs);
        wsplit_kernel<<<g, blk>>>(Wh, p_whs);
        wsplit_kernel<<<g, blk>>>(Wattn, p_was);
    }
    bias_perm_kernel<<<GG / 256, 256>>>(b);

    // phase 1: XW = x' @ Wx'^T + b ; P = AT' @ Wa'^T
    {
        dim3 g(GG / 128, (NB * TT) / 128);
        gemm_mma<128, 128, 2, 4, 1><<<g, 256, SM_P1>>>(p_xs, p_wxs, p_xw, p_bp, nullptr, nullptr, 0);
    }
    {
        dim3 g(GG / 128, (NB * LL) / 128);
        gemm_mma<128, 128, 2, 4, 0><<<g, 256, SM_P1>>>(p_ats, p_was, p_p, nullptr, nullptr, nullptr, 0);
    }

    // phase 2: sequential scan
    for (int t = 0; t < TT; t++) {
        scores_kernel<<<NB, 512>>>();
        combine_kernel<<<NB * 4, 256>>>(t);
        __nv_bfloat16* hc = (t & 1) ? p_hsB : p_hsA;
        __nv_bfloat16* hn = (t & 1) ? p_hsA : p_hsB;
        dim3 g(GG / 64, NB / 64);
        gemm_mma<64, 64, 2, 2, 2><<<g, 128, SM_ST>>>(hc, p_whs, nullptr, p_z, hn, out, t);
    }
}